// round 8
// baseline (speedup 1.0000x reference)
#include <cuda_runtime.h>
#include <cuda_bf16.h>
#include <stdint.h>

#define BATCH   4
#define SEQ     2048
#define DMODEL  1024
#define NHEADS  16
#define HDIM    64
#define MTOT    (BATCH*SEQ)          // 8192

typedef __nv_bfloat16 bf16;

// ---------------- scratch (static device globals; no runtime allocation) ---
__device__ __align__(16) float g_q[(size_t)BATCH*NHEADS*SEQ*HDIM];   // tf32-rounded
__device__ __align__(16) float g_k[(size_t)BATCH*NHEADS*SEQ*HDIM];   // tf32-rounded
__device__ __align__(16) float g_v[(size_t)BATCH*NHEADS*SEQ*HDIM];   // tf32-rounded
// bf16 hi/lo planes
__device__ __align__(16) bf16 g_xh[(size_t)MTOT*DMODEL];
__device__ __align__(16) bf16 g_xl[(size_t)MTOT*DMODEL];
__device__ __align__(16) bf16 g_ah[(size_t)MTOT*DMODEL];             // attn out hi
__device__ __align__(16) bf16 g_al[(size_t)MTOT*DMODEL];             // attn out lo
__device__ __align__(16) bf16 g_wqh[(size_t)3*DMODEL*DMODEL];        // transposed [N][K]
__device__ __align__(16) bf16 g_wql[(size_t)3*DMODEL*DMODEL];
__device__ __align__(16) bf16 g_woh[(size_t)DMODEL*DMODEL];          // transposed [N][K]
__device__ __align__(16) bf16 g_wol[(size_t)DMODEL*DMODEL];

// ---------------- helpers ---------------------------------------------------
__device__ __forceinline__ float f2tf32(float x) {
    uint32_t u;
    asm("cvt.rna.tf32.f32 %0, %1;" : "=r"(u) : "f"(x));
    return __uint_as_float(u);
}
__device__ __forceinline__ void cp16(const void* dst_smem, const void* src) {
    uint32_t d = (uint32_t)__cvta_generic_to_shared(dst_smem);
    asm volatile("cp.async.cg.shared.global [%0], [%1], 16;\n" :: "r"(d), "l"(src));
}
__device__ __forceinline__ void cp_commit() {
    asm volatile("cp.async.commit_group;\n");
}
template <int N>
__device__ __forceinline__ void cp_wait() {
    asm volatile("cp.async.wait_group %0;\n" :: "n"(N));
}
__device__ __forceinline__ void ldsm4(uint32_t& r0, uint32_t& r1, uint32_t& r2,
                                      uint32_t& r3, uint32_t addr) {
    asm volatile("ldmatrix.sync.aligned.m8n8.x4.shared.b16 {%0,%1,%2,%3}, [%4];\n"
                 : "=r"(r0), "=r"(r1), "=r"(r2), "=r"(r3) : "r"(addr));
}

// D += A*B, m16n8k8 tf32 (attention)
__device__ __forceinline__ void mma8(float* c, const float* a, const float* b) {
    const uint32_t* A = reinterpret_cast<const uint32_t*>(a);
    const uint32_t* B = reinterpret_cast<const uint32_t*>(b);
    asm volatile(
        "mma.sync.aligned.m16n8k8.row.col.f32.tf32.tf32.f32 "
        "{%0,%1,%2,%3}, {%4,%5,%6,%7}, {%8,%9}, {%0,%1,%2,%3};\n"
        : "+f"(c[0]), "+f"(c[1]), "+f"(c[2]), "+f"(c[3])
        : "r"(A[0]), "r"(A[1]), "r"(A[2]), "r"(A[3]), "r"(B[0]), "r"(B[1]));
}
// D += A*B, m16n8k16 bf16 (GEMMs)
__device__ __forceinline__ void mma16(float* c, const uint32_t* a,
                                      uint32_t b0, uint32_t b1) {
    asm volatile(
        "mma.sync.aligned.m16n8k16.row.col.f32.bf16.bf16.f32 "
        "{%0,%1,%2,%3}, {%4,%5,%6,%7}, {%8,%9}, {%0,%1,%2,%3};\n"
        : "+f"(c[0]), "+f"(c[1]), "+f"(c[2]), "+f"(c[3])
        : "r"(a[0]), "r"(a[1]), "r"(a[2]), "r"(a[3]), "r"(b0), "r"(b1));
}

__device__ __forceinline__ void split1(float v, bf16& h, bf16& l) {
    h = __float2bfloat16_rn(v);
    l = __float2bfloat16_rn(v - __bfloat162float(h));
}

// ============================================================================
// prep kernels
// ============================================================================
__global__ void __launch_bounds__(256)
split_plain(const float* __restrict__ src, bf16* __restrict__ hi,
            bf16* __restrict__ lo, int n4)
{
    int i = blockIdx.x * blockDim.x + threadIdx.x;
    if (i >= n4) return;
    float4 v = reinterpret_cast<const float4*>(src)[i];
    bf16 h0,l0,h1,l1,h2,l2,h3,l3;
    split1(v.x,h0,l0); split1(v.y,h1,l1); split1(v.z,h2,l2); split1(v.w,h3,l3);
    ushort4 H = make_ushort4(__bfloat16_as_ushort(h0),__bfloat16_as_ushort(h1),
                             __bfloat16_as_ushort(h2),__bfloat16_as_ushort(h3));
    ushort4 L = make_ushort4(__bfloat16_as_ushort(l0),__bfloat16_as_ushort(l1),
                             __bfloat16_as_ushort(l2),__bfloat16_as_ushort(l3));
    reinterpret_cast<ushort4*>(hi)[i] = H;
    reinterpret_cast<ushort4*>(lo)[i] = L;
}

__global__ void __launch_bounds__(256)
split_T(const float* __restrict__ src, bf16* __restrict__ hiT,
        bf16* __restrict__ loT, int K, int N)
{
    __shared__ float t[32][33];
    int n0 = blockIdx.x * 32, k0 = blockIdx.y * 32;
    int tx = threadIdx.x & 31, ty = threadIdx.x >> 5;   // 32 x 8
    #pragma unroll
    for (int j = 0; j < 4; j++)
        t[ty + 8*j][tx] = src[(size_t)(k0 + ty + 8*j)*N + n0 + tx];
    __syncthreads();
    #pragma unroll
    for (int j = 0; j < 4; j++) {
        float v = t[tx][ty + 8*j];
        bf16 h, l; split1(v, h, l);
        size_t o = (size_t)(n0 + ty + 8*j)*K + k0 + tx;
        hiT[o] = h; loT[o] = l;
    }
}

// ============================================================================
// GEMM (bf16x3, ldmatrix frags): C[M,N] = A[M,K] @ B[K,N]
// A planes [M][K], B planes [N][K] (transposed). 128x128 tile, BK=32,
// 256 threads, 2-stage cp.async, single barrier per k-tile.
// Inner mma order is pass-major (HH x4, LH x4, HL x4) per ntp so each
// accumulator is revisited at distance 4, not 1 (hides HMMA latency).
// EPI=0: row-major store. EPI=1: scatter qkv -> g_q/g_k/g_v (tf32-rounded).
// ============================================================================
#define ARS 40                         // bf16 per smem row (32 data + 8 pad)
#define AH_OFF 0
#define AL_OFF (128*ARS)
#define BH_OFF (2*128*ARS)
#define BL_OFF (3*128*ARS)
#define STG_BF (4*128*ARS)             // 20480 bf16 = 40KB per stage
#define GEMM_SMEM_BYTES (2*STG_BF*2)   // 81920

__device__ __forceinline__ void gemm_load_tile(
    bf16* st, const bf16* __restrict__ Ah, const bf16* __restrict__ Al,
    const bf16* __restrict__ BTh, const bf16* __restrict__ BTl,
    int m0, int n0, int k0, int K, int tid)
{
    #pragma unroll
    for (int i = 0; i < 2; i++) {
        int id = tid + i*256;
        int r = id >> 2, c = (id & 3) * 8;
        cp16(st + AH_OFF + r*ARS + c, Ah  + (size_t)(m0+r)*K + k0 + c);
        cp16(st + AL_OFF + r*ARS + c, Al  + (size_t)(m0+r)*K + k0 + c);
        cp16(st + BH_OFF + r*ARS + c, BTh + (size_t)(n0+r)*K + k0 + c);
        cp16(st + BL_OFF + r*ARS + c, BTl + (size_t)(n0+r)*K + k0 + c);
    }
}

template <int EPI>
__global__ void __launch_bounds__(256, 2)
gemm_bf3(const bf16* __restrict__ Ah, const bf16* __restrict__ Al,
         const bf16* __restrict__ BTh, const bf16* __restrict__ BTl,
         float* __restrict__ C, int M, int N, int K)
{
    extern __shared__ __align__(16) char smraw[];
    bf16* smb = reinterpret_cast<bf16*>(smraw);
    const uint32_t sbase = (uint32_t)__cvta_generic_to_shared(smb);

    const int tid  = threadIdx.x;
    const int lane = tid & 31, warp = tid >> 5;
    const int wm = warp & 3, wn = warp >> 2;            // 4 x 2 warp grid
    const int g  = lane >> 2, tg = lane & 3;
    const int m0 = blockIdx.y * 128, n0 = blockIdx.x * 128;

    // ldmatrix per-lane address components
    const int lrow = lane & 15;              // row within 16-row block
    const int lcol = (lane >> 4) << 3;       // 0 or 8 (bf16 col offset)

    float acc[2][8][4];
    #pragma unroll
    for (int i = 0; i < 2; i++)
        #pragma unroll
        for (int j = 0; j < 8; j++)
            #pragma unroll
            for (int e = 0; e < 4; e++) acc[i][j][e] = 0.f;

    const int nk = K >> 5;
    gemm_load_tile(smb, Ah, Al, BTh, BTl, m0, n0, 0, K, tid);
    cp_commit();

    for (int kt = 0; kt < nk; kt++) {
        const uint32_t stoff = (kt & 1) * STG_BF;
        cp_wait<0>();
        __syncthreads();
        if (kt + 1 < nk) {
            gemm_load_tile(smb + ((kt+1) & 1)*STG_BF, Ah, Al, BTh, BTl,
                           m0, n0, (kt+1)*32, K, tid);
            cp_commit();
        }

        #pragma unroll
        for (int s = 0; s < 2; s++) {
            const int ko = s*16;
            uint32_t ah[2][4], al[2][4];
            #pragma unroll
            for (int mt = 0; mt < 2; mt++) {
                int rb = wm*32 + mt*16 + lrow;
                uint32_t base = sbase + ((stoff + rb*ARS + ko + lcol) << 1);
                ldsm4(ah[mt][0], ah[mt][1], ah[mt][2], ah[mt][3], base + (AH_OFF<<1));
                ldsm4(al[mt][0], al[mt][1], al[mt][2], al[mt][3], base + (AL_OFF<<1));
            }
            #pragma unroll
            for (int ntp = 0; ntp < 4; ntp++) {
                int cb = wn*64 + ntp*16 + lrow;
                uint32_t base = sbase + ((stoff + cb*ARS + ko + lcol) << 1);
                uint32_t bh0, bh1, bh2, bh3, bl0, bl1, bl2, bl3;
                ldsm4(bh0, bh1, bh2, bh3, base + (BH_OFF<<1));
                ldsm4(bl0, bl1, bl2, bl3, base + (BL_OFF<<1));
                // pass-major: 4 distinct accumulators per pass (chain dist 4)
                mma16(acc[0][2*ntp  ], ah[0], bh0, bh2);   // HH
                mma16(acc[0][2*ntp+1], ah[0], bh1, bh3);
                mma16(acc[1][2*ntp  ], ah[1], bh0, bh2);
                mma16(acc[1][2*ntp+1], ah[1], bh1, bh3);
                mma16(acc[0][2*ntp  ], al[0], bh0, bh2);   // LH
                mma16(acc[0][2*ntp+1], al[0], bh1, bh3);
                mma16(acc[1][2*ntp  ], al[1], bh0, bh2);
                mma16(acc[1][2*ntp+1], al[1], bh1, bh3);
                mma16(acc[0][2*ntp  ], ah[0], bl0, bl2);   // HL
                mma16(acc[0][2*ntp+1], ah[0], bl1, bl3);
                mma16(acc[1][2*ntp  ], ah[1], bl0, bl2);
                mma16(acc[1][2*ntp+1], ah[1], bl1, bl3);
            }
        }
    }

    // epilogue (float2 stores)
    #pragma unroll
    for (int mt = 0; mt < 2; mt++) {
        #pragma unroll
        for (int nt = 0; nt < 8; nt++) {
            #pragma unroll
            for (int half = 0; half < 2; half++) {
                int r = m0 + wm*32 + mt*16 + g + (half ? 8 : 0);
                int c = n0 + wn*64 + nt*8 + 2*tg;
                float2 v = make_float2(acc[mt][nt][2*half], acc[mt][nt][2*half+1]);
                if (EPI == 0) {
                    *reinterpret_cast<float2*>(C + (size_t)r*N + c) = v;
                } else {
                    // pre-round q/k/v to tf32 so attention skips all cvts
                    v.x = f2tf32(v.x); v.y = f2tf32(v.y);
                    int b = r >> 11, s = r & (SEQ-1);
                    int which = c >> 10, rem = c & (DMODEL-1);
                    int h = rem >> 6, d = rem & (HDIM-1);
                    float* dst = (which == 0) ? g_q : (which == 1) ? g_k : g_v;
                    *reinterpret_cast<float2*>(
                        dst + ((size_t)((b*NHEADS + h)*SEQ + s))*HDIM + d) = v;
                }
            }
        }
    }
}

// ============================================================================
// Flash attention (tf32 mma): grid (S/128, B*H), 128 threads (4 warps),
// 3 CTAs/SM. Each warp: 32 q-rows. Q frags re-loaded per kt via __ldg
// (L1-resident; KV cp.async.cg bypasses L1). K tile stride 68 and V tile
// stride 72 give conflict-free banks for both frag patterns. Scale folded
// into the exp argument. Epilogue writes bf16 hi/lo planes for GEMM3.
// ============================================================================
#define KPAD 68                          // banks (4g+tg) all distinct
#define VPAD 72                          // banks (8tg+g) all distinct
#define KTILE (64*KPAD)
#define KVSTG (64*KPAD + 64*VPAD)        // 8960 floats
#define ATTN_SMEM_BYTES (2*KVSTG*4)      // 71680

__device__ __forceinline__ void attn_load_kv(
    float* Ks, float* Vs, size_t hbase, int kt, int tid)
{
    #pragma unroll
    for (int j = 0; j < 8; j++) {
        int id = tid + j*128;
        int r = id >> 4, c4 = (id & 15) * 4;
        size_t off = hbase + (size_t)(kt*64 + r)*HDIM + c4;
        cp16(Ks + r*KPAD + c4, g_k + off);
        cp16(Vs + r*VPAD + c4, g_v + off);
    }
}

__global__ void __launch_bounds__(128, 3)
flashattn()
{
    extern __shared__ float sm[];

    const int tid  = threadIdx.x;
    const int lane = tid & 31, warp = tid >> 5;        // 4 warps
    const int g  = lane >> 2, tg = lane & 3;
    const int bh = blockIdx.y;
    const int q0 = blockIdx.x * 128;
    const int rb = warp * 32;                          // warp's 32 q-rows
    const size_t hbase = (size_t)bh * SEQ * HDIM;
    const float scale = 0.125f;                        // 1/sqrt(64)

    // prefetch KV tile 0
    attn_load_kv(sm, sm + KTILE, hbase, 0, tid);
    cp_commit();

    // per-thread Q row pointers (rows fixed for whole kernel)
    const float* qp[2][2];
    #pragma unroll
    for (int mt = 0; mt < 2; mt++) {
        qp[mt][0] = g_q + hbase + (size_t)(q0 + rb + mt*16 + g    )*HDIM;
        qp[mt][1] = g_q + hbase + (size_t)(q0 + rb + mt*16 + g + 8)*HDIM;
    }

    float mrow[2][2], lrow[2][2];
    #pragma unroll
    for (int mt = 0; mt < 2; mt++) {
        mrow[mt][0] = -1e30f; mrow[mt][1] = -1e30f;
        lrow[mt][0] = 0.f;    lrow[mt][1] = 0.f;
    }
    float o[2][8][4];
    #pragma unroll
    for (int mt = 0; mt < 2; mt++)
        #pragma unroll
        for (int nt = 0; nt < 8; nt++)
            #pragma unroll
            for (int e = 0; e < 4; e++) o[mt][nt][e] = 0.f;

    const int NKT = SEQ/64;
    for (int kt = 0; kt < NKT; kt++) {
        float* Ks = sm + (kt & 1)*KVSTG;
        float* Vs = Ks + KTILE;
        cp_wait<0>();
        __syncthreads();
        if (kt + 1 < NKT) {
            float* Ksn = sm + ((kt+1) & 1)*KVSTG;
            attn_load_kv(Ksn, Ksn + KTILE, hbase, kt+1, tid);
            cp_commit();
        }

        // S = Q @ K^T : warp computes 32 x 64 (unscaled logits)
        float sacc[2][8][4];
        #pragma unroll
        for (int mt = 0; mt < 2; mt++)
            #pragma unroll
            for (int nt = 0; nt < 8; nt++)
                #pragma unroll
                for (int e = 0; e < 4; e++) sacc[mt][nt][e] = 0.f;

        #pragma unroll
        for (int ks = 0; ks < 8; ks++) {
            const int kc = ks*8;
            float af[2][4];
            #pragma unroll
            for (int mt = 0; mt < 2; mt++) {
                af[mt][0] = __ldg(qp[mt][0] + kc + tg);
                af[mt][1] = __ldg(qp[mt][1] + kc + tg);
                af[mt][2] = __ldg(qp[mt][0] + kc + tg + 4);
                af[mt][3] = __ldg(qp[mt][1] + kc + tg + 4);
            }
            #pragma unroll
            for (int nt = 0; nt < 8; nt++) {
                float bf[2];
                bf[0] = Ks[(nt*8+g)*KPAD + kc + tg  ];
                bf[1] = Ks[(nt*8+g)*KPAD + kc + tg+4];
                mma8(sacc[0][nt], af[0], bf);
                mma8(sacc[1][nt], af[1], bf);
            }
        }

        // online softmax per m-frag (scale folded into exp argument)
        #pragma unroll
        for (int mt = 0; mt < 2; mt++) {
            float mx0 = -1e30f, mx1 = -1e30f;
            #pragma unroll
            for (int nt = 0; nt < 8; nt++) {
                mx0 = fmaxf(mx0, fmaxf(sacc[mt][nt][0], sacc[mt][nt][1]));
                mx1 = fmaxf(mx1, fmaxf(sacc[mt][nt][2], sacc[mt][nt][3]));
            }
            mx0 = fmaxf(mx0, __shfl_xor_sync(0xffffffffu, mx0, 1));
            mx0 = fmaxf(mx0, __shfl_xor_sync(0xffffffffu, mx0, 2));
            mx1 = fmaxf(mx1, __shfl_xor_sync(0xffffffffu, mx1, 1));
            mx1 = fmaxf(mx1, __shfl_xor_sync(0xffffffffu, mx1, 2));
            float mn0 = fmaxf(mrow[mt][0], mx0), mn1 = fmaxf(mrow[mt][1], mx1);
            float a0 = __expf((mrow[mt][0] - mn0)*scale);
            float a1 = __expf((mrow[mt][1] - mn1)*scale);
            float mns0 = mn0*scale, mns1 = mn1*scale;
            float s0 = 0.f, s1 = 0.f;
            #pragma unroll
            for (int nt = 0; nt < 8; nt++) {
                sacc[mt][nt][0] = __expf(fmaf(sacc[mt][nt][0], scale, -mns0)); s0 += sacc[mt][nt][0];
                sacc[mt][nt][1] = __expf(fmaf(sacc[mt][nt][1], scale, -mns0)); s0 += sacc[mt][nt][1];
                sacc[mt][nt][2] = __expf(fmaf(sacc[mt][nt][2], scale, -mns1)); s1 += sacc[mt][nt][2];
                sacc[mt][nt][3] = __expf(fmaf(sacc[mt][nt][3], scale, -mns1)); s1 += sacc[mt][nt][3];
            }
            s0 += __shfl_xor_sync(0xffffffffu, s0, 1);
            s0 += __shfl_xor_sync(0xffffffffu, s0, 2);
            s1 += __shfl_xor_sync(0xffffffffu, s1, 1);
            s1 += __shfl_xor_sync(0xffffffffu, s1, 2);
            lrow[mt][0] = lrow[mt][0]*a0 + s0;
            lrow[mt][1] = lrow[mt][1]*a1 + s1;
            mrow[mt][0] = mn0; mrow[mt][1] = mn1;
            #pragma unroll
            for (int nt = 0; nt < 8; nt++) {
                o[mt][nt][0] *= a0; o[mt][nt][1] *= a0;
                o[mt][nt][2] *= a1; o[mt][nt][3] *= a1;
            }
        }

        // O += P @ V : P A-frags built from sacc via quad shuffles
        const int src0 = (lane & 28) | (tg >> 1);
        const int src1 = src0 | 2;
        #pragma unroll
        for (int ks = 0; ks < 8; ks++) {
            const int kc = ks*8;
            float pa[2][4];
            #pragma unroll
            for (int mt = 0; mt < 2; mt++) {
                float x0 = __shfl_sync(0xffffffffu, sacc[mt][ks][0], src0);
                float x1 = __shfl_sync(0xffffffffu, sacc[mt][ks][1], src0);
                float x2 = __shfl_sync(0xffffffffu, sacc[mt][ks][2], src0);
                float x3 = __shfl_sync(0xffffffffu, sacc[mt][ks][3], src0);
                float y0 = __shfl_sync(0xffffffffu, sacc[mt][ks][0], src1);
                float y1 = __shfl_sync(0xffffffffu, sacc[mt][ks][1], src1);
                float y2 = __shfl_sync(0xffffffffu, sacc[mt][ks][2], src1);
                float y3 = __shfl_sync(0xffffffffu, sacc[mt][ks][3], src1);
                pa[mt][0] = f2tf32((tg & 1) ? x1 : x0);
                pa[mt][1] = f2tf32((tg & 1) ? x3 : x2);
                pa[mt][2] = f2tf32((tg & 1) ? y1 : y0);
                pa[mt][3] = f2tf32((tg & 1) ? y3 : y2);
            }
            #pragma unroll
            for (int nt = 0; nt < 8; nt++) {
                float bf[2];
                bf[0] = Vs[(kc+tg  )*VPAD + nt*8 + g];
                bf[1] = Vs[(kc+tg+4)*VPAD + nt*8 + g];
                mma8(o[0][nt], pa[0], bf);
                mma8(o[1][nt], pa[1], bf);
            }
        }
    }

    // epilogue: O /= l ; write bf16 hi/lo planes [B,S,DMODEL] for GEMM3
    const int b = bh / NHEADS, h = bh % NHEADS;
    #pragma unroll
    for (int mt = 0; mt < 2; mt++) {
        float inv0 = 1.f / lrow[mt][0], inv1 = 1.f / lrow[mt][1];
        #pragma unroll
        for (int nt = 0; nt < 8; nt++) {
            int c = h*HDIM + nt*8 + 2*tg;
            size_t base0 = ((size_t)(b*SEQ + q0 + rb + mt*16 + g    ))*DMODEL + c;
            size_t base1 = ((size_t)(b*SEQ + q0 + rb + mt*16 + g + 8))*DMODEL + c;
            bf16 h0,l0,h1,l1;
            split1(o[mt][nt][0]*inv0, h0, l0);
            split1(o[mt][nt][1]*inv0, h1, l1);
            __nv_bfloat162 H, L;
            H.x = h0; H.y = h1; L.x = l0; L.y = l1;
            *reinterpret_cast<__nv_bfloat162*>(g_ah + base0) = H;
            *reinterpret_cast<__nv_bfloat162*>(g_al + base0) = L;
            split1(o[mt][nt][2]*inv1, h0, l0);
            split1(o[mt][nt][3]*inv1, h1, l1);
            H.x = h0; H.y = h1; L.x = l0; L.y = l1;
            *reinterpret_cast<__nv_bfloat162*>(g_ah + base1) = H;
            *reinterpret_cast<__nv_bfloat162*>(g_al + base1) = L;
        }
    }
}

// ============================================================================
extern "C" void kernel_launch(void* const* d_in, const int* in_sizes, int n_in,
                              void* d_out, int out_size)
{
    (void)in_sizes; (void)n_in; (void)out_size;
    const float* x    = (const float*)d_in[0];
    const float* wqkv = (const float*)d_in[1];
    const float* wout = (const float*)d_in[2];
    float* out = (float*)d_out;

    void *xh, *xl, *ah, *al, *wqh, *wql, *woh, *wol;
    cudaGetSymbolAddress(&xh, g_xh);   cudaGetSymbolAddress(&xl, g_xl);
    cudaGetSymbolAddress(&ah, g_ah);   cudaGetSymbolAddress(&al, g_al);
    cudaGetSymbolAddress(&wqh, g_wqh); cudaGetSymbolAddress(&wql, g_wql);
    cudaGetSymbolAddress(&woh, g_woh); cudaGetSymbolAddress(&wol, g_wol);

    cudaFuncSetAttribute((const void*)gemm_bf3<1>,
                         cudaFuncAttributeMaxDynamicSharedMemorySize, GEMM_SMEM_BYTES);
    cudaFuncSetAttribute((const void*)gemm_bf3<0>,
                         cudaFuncAttributeMaxDynamicSharedMemorySize, GEMM_SMEM_BYTES);
    cudaFuncSetAttribute((const void*)flashattn,
                         cudaFuncAttributeMaxDynamicSharedMemorySize, ATTN_SMEM_BYTES);

    // prep: split x; split+transpose weights
    split_plain<<<(MTOT*DMODEL/4 + 255)/256, 256>>>(x, (bf16*)xh, (bf16*)xl, MTOT*DMODEL/4);
    split_T<<<dim3(3*DMODEL/32, DMODEL/32), 256>>>(wqkv, (bf16*)wqh, (bf16*)wql, DMODEL, 3*DMODEL);
    split_T<<<dim3(DMODEL/32, DMODEL/32), 256>>>(wout, (bf16*)woh, (bf16*)wol, DMODEL, DMODEL);

    // 1) QKV projection -> scatter (tf32-rounded) to g_q/g_k/g_v
    gemm_bf3<1><<<dim3(3*DMODEL/128, MTOT/128), 256, GEMM_SMEM_BYTES>>>(
        (const bf16*)xh, (const bf16*)xl, (const bf16*)wqh, (const bf16*)wql,
        nullptr, MTOT, 3*DMODEL, DMODEL);

    // 2) flash attention -> g_ah/g_al (bf16 hi/lo planes)
    flashattn<<<dim3(SEQ/128, BATCH*NHEADS), 128, ATTN_SMEM_BYTES>>>();

    // 3) out projection -> d_out
    gemm_bf3<0><<<dim3(DMODEL/128, MTOT/128), 256, GEMM_SMEM_BYTES>>>(
        (const bf16*)ah, (const bf16*)al, (const bf16*)woh, (const bf16*)wol,
        out, MTOT, DMODEL, DMODEL);
}